// round 1
// baseline (speedup 1.0000x reference)
#include <cuda_runtime.h>
#include <math.h>

#define LDIM   16
#define HLDIM  512
#define DDIM   64
#define BSZ    128
#define GSZ    100
#define OUTS   8450   // 64 + 1 + 4096 + 64 + 4096 + 64 + 64 + 1

// Scratch (no cudaMalloc allowed)
__device__ float g_h0[BSZ * HLDIM];
__device__ float g_h1[BSZ * HLDIM];
__device__ float g_h2[BSZ * HLDIM];
__device__ float g_wab[BSZ * OUTS];

// ----------------------------------------------------------------------------
// Generic fp32 tiled GEMM: C[M,N] = A[M,K] @ B[K,N] + bias[N], optional leaky.
// M is assumed to be a multiple of BM (M=128 here). N is guarded.
// ----------------------------------------------------------------------------
template<int BM, int BN, int BK, int TM, int TN, int ACT>
__launch_bounds__((BM / TM) * (BN / TN))
__global__ void sgemm_bias(const float* __restrict__ A,
                           const float* __restrict__ B,
                           const float* __restrict__ bias,
                           float* __restrict__ C,
                           int M, int N, int K)
{
    constexpr int NT = (BM / TM) * (BN / TN);
    __shared__ float As[BK][BM];
    __shared__ float Bs[BK][BN];

    const int bm = blockIdx.y * BM;
    const int bn = blockIdx.x * BN;
    const int tid = threadIdx.x;
    const int tc = (tid % (BN / TN)) * TN;
    const int tr = (tid / (BN / TN)) * TM;

    float acc[TM][TN];
#pragma unroll
    for (int i = 0; i < TM; i++)
#pragma unroll
        for (int j = 0; j < TN; j++) acc[i][j] = 0.0f;

    for (int k0 = 0; k0 < K; k0 += BK) {
        for (int i = tid; i < BM * BK; i += NT) {
            int m = i / BK, kk = i % BK;
            As[kk][m] = A[(bm + m) * K + (k0 + kk)];
        }
        for (int i = tid; i < BK * BN; i += NT) {
            int kk = i / BN, n = i % BN;
            int gn = bn + n;
            Bs[kk][n] = (gn < N) ? B[(k0 + kk) * N + gn] : 0.0f;
        }
        __syncthreads();

#pragma unroll
        for (int kk = 0; kk < BK; kk++) {
            float av[TM], bv[TN];
#pragma unroll
            for (int i = 0; i < TM; i++) av[i] = As[kk][tr + i];
#pragma unroll
            for (int j = 0; j < TN; j++) bv[j] = Bs[kk][tc + j];
#pragma unroll
            for (int i = 0; i < TM; i++)
#pragma unroll
                for (int j = 0; j < TN; j++)
                    acc[i][j] = fmaf(av[i], bv[j], acc[i][j]);
        }
        __syncthreads();
    }

#pragma unroll
    for (int i = 0; i < TM; i++) {
        int gm = bm + tr + i;
#pragma unroll
        for (int j = 0; j < TN; j++) {
            int gn = bn + tc + j;
            if (gn < N) {
                float v = acc[i][j] + bias[gn];
                if (ACT) v = (v > 0.0f) ? v : 0.01f * v;
                C[gm * N + gn] = v;
            }
        }
    }
}

// ----------------------------------------------------------------------------
// Decoder: one block per b (128 blocks), 128 threads (100 active, one per g).
// wab row (8450 floats) staged into smem at aligned offsets; per-thread
// activation vectors live in smem columns (stride 128) so loops need no
// full unrolling (keeps registers ~90 and I-cache small).
//
// smem layout (floats):
//   [0,64)        w0
//   [64,4160)     W1  (64x64, row-major)
//   [4160,8256)   W2
//   [8256,8320)   w3
//   [8320,8384)   b1
//   [8384,8448)   b2
//   [8448]        b0 scalar, [8449] b3 scalar, [8450,8452) pad
//   [8452, 8452+64*128)  x vectors, x[i] for thread t at 8452 + i*128 + t
// ----------------------------------------------------------------------------
#define DEC_NT 128
#define DEC_SMEM_FLOATS (8452 + 64 * DEC_NT)

__global__ __launch_bounds__(DEC_NT)
void decoder_kernel(const float* __restrict__ logP,
                    const float* __restrict__ wab,
                    float* __restrict__ out)
{
    extern __shared__ float s[];
    float* s_w0 = s;
    float* s_W1 = s + 64;
    float* s_W2 = s + 4160;
    float* s_w3 = s + 8256;
    float* s_b1 = s + 8320;
    float* s_b2 = s + 8384;
    float* s_sc = s + 8448;
    float* s_x  = s + 8452;

    const int b = blockIdx.x;
    const int tid = threadIdx.x;
    const float* __restrict__ src = wab + (size_t)b * OUTS;

    // stage weights
    if (tid < 64) {
        s_w0[tid] = src[tid];
        s_b1[tid] = src[4161 + tid];
        s_b2[tid] = src[8321 + tid];
        s_w3[tid] = src[8385 + tid];
    }
    for (int i = tid; i < 4096; i += DEC_NT) {
        s_W1[i] = src[65 + i];
        s_W2[i] = src[4225 + i];
    }
    if (tid == 0) { s_sc[0] = src[64]; s_sc[1] = src[8449]; }
    __syncthreads();

    if (tid >= GSZ) return;

    const float x_in = logP[b * GSZ + tid] * (1.0f / 3.0f);
    const float b0 = s_sc[0];
    const float b3 = s_sc[1];

    // layer 0: x1 = sin(30 * (x * w0 + b0))
#pragma unroll
    for (int j = 0; j < 64; j++) {
        float v = 30.0f * fmaf(x_in, s_w0[j], b0);
        s_x[j * DEC_NT + tid] = sinf(v);
    }

    float acc[64];

    // layer 1
#pragma unroll
    for (int j = 0; j < 64; j++) acc[j] = s_b1[j];
#pragma unroll 4
    for (int i = 0; i < 64; i++) {
        float a = s_x[i * DEC_NT + tid];
        const float4* wrow = (const float4*)&s_W1[i * 64];
#pragma unroll
        for (int j4 = 0; j4 < 16; j4++) {
            float4 wv = wrow[j4];
            acc[j4 * 4 + 0] = fmaf(a, wv.x, acc[j4 * 4 + 0]);
            acc[j4 * 4 + 1] = fmaf(a, wv.y, acc[j4 * 4 + 1]);
            acc[j4 * 4 + 2] = fmaf(a, wv.z, acc[j4 * 4 + 2]);
            acc[j4 * 4 + 3] = fmaf(a, wv.w, acc[j4 * 4 + 3]);
        }
    }
#pragma unroll
    for (int j = 0; j < 64; j++) s_x[j * DEC_NT + tid] = sinf(acc[j]);

    // layer 2
#pragma unroll
    for (int j = 0; j < 64; j++) acc[j] = s_b2[j];
#pragma unroll 4
    for (int i = 0; i < 64; i++) {
        float a = s_x[i * DEC_NT + tid];
        const float4* wrow = (const float4*)&s_W2[i * 64];
#pragma unroll
        for (int j4 = 0; j4 < 16; j4++) {
            float4 wv = wrow[j4];
            acc[j4 * 4 + 0] = fmaf(a, wv.x, acc[j4 * 4 + 0]);
            acc[j4 * 4 + 1] = fmaf(a, wv.y, acc[j4 * 4 + 1]);
            acc[j4 * 4 + 2] = fmaf(a, wv.z, acc[j4 * 4 + 2]);
            acc[j4 * 4 + 3] = fmaf(a, wv.w, acc[j4 * 4 + 3]);
        }
    }

    // layer 3 (scalar output, no sin)
    float o = b3;
#pragma unroll
    for (int i = 0; i < 64; i++)
        o = fmaf(sinf(acc[i]), s_w3[i], o);

    out[b * GSZ + tid] = fmaf(o, 500.0f, 1500.0f);
}

// ----------------------------------------------------------------------------
extern "C" void kernel_launch(void* const* d_in, const int* in_sizes, int n_in,
                              void* d_out, int out_size)
{
    const float* z    = (const float*)d_in[0];
    const float* logP = (const float*)d_in[1];
    const float* hW0  = (const float*)d_in[2];
    const float* hb0  = (const float*)d_in[3];
    const float* hW1  = (const float*)d_in[4];
    const float* hb1  = (const float*)d_in[5];
    const float* hW2  = (const float*)d_in[6];
    const float* hb2  = (const float*)d_in[7];
    const float* hWo  = (const float*)d_in[8];
    const float* hbo  = (const float*)d_in[9];
    float* out = (float*)d_out;

    float *h0p, *h1p, *h2p, *wabp;
    cudaGetSymbolAddress((void**)&h0p, g_h0);
    cudaGetSymbolAddress((void**)&h1p, g_h1);
    cudaGetSymbolAddress((void**)&h2p, g_h2);
    cudaGetSymbolAddress((void**)&wabp, g_wab);

    // hypernet on B=128 unique rows only
    sgemm_bias<32, 32, 16, 2, 2, 1><<<dim3(HLDIM / 32, BSZ / 32), 256>>>(
        z, hW0, hb0, h0p, BSZ, HLDIM, LDIM);
    sgemm_bias<32, 32, 16, 2, 2, 1><<<dim3(HLDIM / 32, BSZ / 32), 256>>>(
        h0p, hW1, hb1, h1p, BSZ, HLDIM, HLDIM);
    sgemm_bias<32, 32, 16, 2, 2, 1><<<dim3(HLDIM / 32, BSZ / 32), 256>>>(
        h1p, hW2, hb2, h2p, BSZ, HLDIM, HLDIM);
    sgemm_bias<64, 64, 16, 4, 4, 0><<<dim3((OUTS + 63) / 64, BSZ / 64), 256>>>(
        h2p, hWo, hbo, wabp, BSZ, OUTS, HLDIM);

    // decoder
    const int smem_bytes = DEC_SMEM_FLOATS * (int)sizeof(float);
    cudaFuncSetAttribute(decoder_kernel,
                         cudaFuncAttributeMaxDynamicSharedMemorySize, smem_bytes);
    decoder_kernel<<<BSZ, DEC_NT, smem_bytes>>>(logP, wabp, out);
}

// round 2
// speedup vs baseline: 2.5531x; 2.5531x over previous
#include <cuda_runtime.h>
#include <math.h>

#define LDIM   16
#define HLDIM  512
#define BSZ    128
#define GSZ    100
#define OUTS   8450   // 64 + 1 + 4096 + 64 + 4096 + 64 + 64 + 1

// Scratch (no cudaMalloc allowed)
__device__ float g_h0[BSZ * HLDIM];
__device__ float g_h1[BSZ * HLDIM];
__device__ float g_h2[BSZ * HLDIM];
__device__ float g_wab[BSZ * OUTS];
__device__ float g_part[4 * BSZ * OUTS];   // split-K partials (max: wab S=4)

// ----------------------------------------------------------------------------
// Tiled fp32 GEMM with optional split-K.
// SPLITS==1: C[M,N] = act(A@B + bias) written directly.
// SPLITS>1 : raw partials written to C[z][M][N]; bias/act applied by reduce.
// ----------------------------------------------------------------------------
template<int BM, int BN, int BK, int TM, int TN, int ACT, int SPLITS>
__launch_bounds__((BM / TM) * (BN / TN))
__global__ void gemm_k(const float* __restrict__ A,
                       const float* __restrict__ B,
                       const float* __restrict__ bias,
                       float* __restrict__ C,
                       int M, int N, int K)
{
    constexpr int NT = (BM / TM) * (BN / TN);
    __shared__ float As[BK][BM + 4];
    __shared__ float Bs[BK][BN];

    const int bm = blockIdx.y * BM;
    const int bn = blockIdx.x * BN;
    const int tid = threadIdx.x;
    const int tc = (tid % (BN / TN)) * TN;
    const int tr = (tid / (BN / TN)) * TM;

    const int Kc = K / SPLITS;
    const int kbase = blockIdx.z * Kc;

    float acc[TM][TN];
#pragma unroll
    for (int i = 0; i < TM; i++)
#pragma unroll
        for (int j = 0; j < TN; j++) acc[i][j] = 0.0f;

    for (int k0 = 0; k0 < Kc; k0 += BK) {
        // A tile: float4 global loads (rows are 16B aligned: K % 4 == 0)
#pragma unroll
        for (int idx = tid; idx < BM * (BK / 4); idx += NT) {
            int m = idx / (BK / 4);
            int kq = idx % (BK / 4);
            float4 v = *(const float4*)&A[(size_t)(bm + m) * K + kbase + k0 + kq * 4];
            As[kq * 4 + 0][m] = v.x;
            As[kq * 4 + 1][m] = v.y;
            As[kq * 4 + 2][m] = v.z;
            As[kq * 4 + 3][m] = v.w;
        }
        // B tile: scalar coalesced loads (B rows not 16B aligned for N=8450)
#pragma unroll
        for (int idx = tid; idx < BK * BN; idx += NT) {
            int kk = idx / BN;
            int n = idx % BN;
            int gn = bn + n;
            Bs[kk][n] = (gn < N) ? B[(size_t)(kbase + k0 + kk) * N + gn] : 0.0f;
        }
        __syncthreads();

#pragma unroll
        for (int kk = 0; kk < BK; kk++) {
            float av[TM], bv[TN];
            if constexpr (TM % 4 == 0) {
#pragma unroll
                for (int i = 0; i < TM; i += 4) {
                    float4 v = *(const float4*)&As[kk][tr + i];
                    av[i] = v.x; av[i + 1] = v.y; av[i + 2] = v.z; av[i + 3] = v.w;
                }
            } else {
#pragma unroll
                for (int i = 0; i < TM; i++) av[i] = As[kk][tr + i];
            }
            if constexpr (TN % 4 == 0) {
#pragma unroll
                for (int j = 0; j < TN; j += 4) {
                    float4 v = *(const float4*)&Bs[kk][tc + j];
                    bv[j] = v.x; bv[j + 1] = v.y; bv[j + 2] = v.z; bv[j + 3] = v.w;
                }
            } else {
#pragma unroll
                for (int j = 0; j < TN; j++) bv[j] = Bs[kk][tc + j];
            }
#pragma unroll
            for (int i = 0; i < TM; i++)
#pragma unroll
                for (int j = 0; j < TN; j++)
                    acc[i][j] = fmaf(av[i], bv[j], acc[i][j]);
        }
        __syncthreads();
    }

    if constexpr (SPLITS == 1) {
#pragma unroll
        for (int i = 0; i < TM; i++) {
            int gm = bm + tr + i;
#pragma unroll
            for (int j = 0; j < TN; j++) {
                int gn = bn + tc + j;
                if (gn < N) {
                    float v = acc[i][j] + bias[gn];
                    if (ACT) v = (v > 0.0f) ? v : 0.01f * v;
                    C[(size_t)gm * N + gn] = v;
                }
            }
        }
    } else {
        float* __restrict__ P = C + (size_t)blockIdx.z * M * N;
#pragma unroll
        for (int i = 0; i < TM; i++) {
            int gm = bm + tr + i;
#pragma unroll
            for (int j = 0; j < TN; j++) {
                int gn = bn + tc + j;
                if (gn < N) P[(size_t)gm * N + gn] = acc[i][j];
            }
        }
    }
}

// ----------------------------------------------------------------------------
// Split-K reduce + bias + optional leaky relu
// ----------------------------------------------------------------------------
template<int ACT, int SPLITS>
__global__ void reduce_bias(const float* __restrict__ P,
                            const float* __restrict__ bias,
                            float* __restrict__ C, int M, int N)
{
    int i = blockIdx.x * blockDim.x + threadIdx.x;
    int MN = M * N;
    if (i >= MN) return;
    float s = 0.0f;
#pragma unroll
    for (int z = 0; z < SPLITS; z++) s += P[(size_t)z * MN + i];
    s += bias[i % N];
    if (ACT) s = (s > 0.0f) ? s : 0.01f * s;
    C[i] = s;
}

// ----------------------------------------------------------------------------
// Decoder: one block per b, 512 threads = 4 j-groups x 128 g-lanes.
// Each group computes 16 of the 64 hidden neurons per layer; activations
// exchanged through smem between layers.
//
// smem layout (floats):
//   [0,64) w0 | [64,4160) W1 | [4160,8256) W2 | [8256,8320) w3
//   [8320,8384) b1 | [8384,8448) b2 | [8448] b0, [8449] b3, pad to 8452
//   [8452, 8452+64*128) x vectors: x[i] for lane t at 8452 + i*128 + t
// ----------------------------------------------------------------------------
#define DEC_NT 512
#define DEC_SMEM_FLOATS (8452 + 64 * 128)

__global__ __launch_bounds__(DEC_NT)
void decoder_kernel(const float* __restrict__ logP,
                    const float* __restrict__ wab,
                    float* __restrict__ out)
{
    extern __shared__ float s[];
    float* s_w0 = s;
    float* s_W1 = s + 64;
    float* s_W2 = s + 4160;
    float* s_w3 = s + 8256;
    float* s_b1 = s + 8320;
    float* s_b2 = s + 8384;
    float* s_sc = s + 8448;
    float* s_x  = s + 8452;

    const int b = blockIdx.x;
    const int tid = threadIdx.x;
    const int lane = tid & 127;
    const int grp = tid >> 7;          // 0..3
    const int j0 = grp * 16;
    const float* __restrict__ src = wab + (size_t)b * OUTS;

    // stage weights (all 512 threads)
    if (tid < 64) {
        s_w0[tid] = src[tid];
        s_b1[tid] = src[4161 + tid];
        s_b2[tid] = src[8321 + tid];
        s_w3[tid] = src[8385 + tid];
    }
    for (int i = tid; i < 4096; i += DEC_NT) {
        s_W1[i] = src[65 + i];
        s_W2[i] = src[4225 + i];
    }
    if (tid == 0) { s_sc[0] = src[64]; s_sc[1] = src[8449]; }
    __syncthreads();

    const bool active = (lane < GSZ);
    float x_in = 0.0f;
    if (active) x_in = logP[b * GSZ + lane] * (1.0f / 3.0f);
    const float b0 = s_sc[0];
    const float b3 = s_sc[1];

    // layer 0: x1 = sin(30 * (x * w0 + b0))   (group computes its 16 neurons)
    if (active) {
#pragma unroll
        for (int jj = 0; jj < 16; jj++) {
            float v = 30.0f * fmaf(x_in, s_w0[j0 + jj], b0);
            s_x[(j0 + jj) * 128 + lane] = sinf(v);
        }
    }
    __syncthreads();

    float acc[16];

    // layer 1
    if (active) {
#pragma unroll
        for (int jj = 0; jj < 16; jj++) acc[jj] = s_b1[j0 + jj];
#pragma unroll 8
        for (int i = 0; i < 64; i++) {
            float a = s_x[i * 128 + lane];
            const float4* wrow = (const float4*)&s_W1[i * 64 + j0];
#pragma unroll
            for (int q = 0; q < 4; q++) {
                float4 wv = wrow[q];
                acc[q * 4 + 0] = fmaf(a, wv.x, acc[q * 4 + 0]);
                acc[q * 4 + 1] = fmaf(a, wv.y, acc[q * 4 + 1]);
                acc[q * 4 + 2] = fmaf(a, wv.z, acc[q * 4 + 2]);
                acc[q * 4 + 3] = fmaf(a, wv.w, acc[q * 4 + 3]);
            }
        }
    }
    __syncthreads();
    if (active) {
#pragma unroll
        for (int jj = 0; jj < 16; jj++)
            s_x[(j0 + jj) * 128 + lane] = sinf(acc[jj]);
    }
    __syncthreads();

    // layer 2
    if (active) {
#pragma unroll
        for (int jj = 0; jj < 16; jj++) acc[jj] = s_b2[j0 + jj];
#pragma unroll 8
        for (int i = 0; i < 64; i++) {
            float a = s_x[i * 128 + lane];
            const float4* wrow = (const float4*)&s_W2[i * 64 + j0];
#pragma unroll
            for (int q = 0; q < 4; q++) {
                float4 wv = wrow[q];
                acc[q * 4 + 0] = fmaf(a, wv.x, acc[q * 4 + 0]);
                acc[q * 4 + 1] = fmaf(a, wv.y, acc[q * 4 + 1]);
                acc[q * 4 + 2] = fmaf(a, wv.z, acc[q * 4 + 2]);
                acc[q * 4 + 3] = fmaf(a, wv.w, acc[q * 4 + 3]);
            }
        }
    }
    __syncthreads();
    if (active) {
#pragma unroll
        for (int jj = 0; jj < 16; jj++)
            s_x[(j0 + jj) * 128 + lane] = sinf(acc[jj]);
    }
    __syncthreads();

    // layer 3 (scalar out): group 0 reduces
    if (grp == 0 && active) {
        float o = b3;
#pragma unroll 8
        for (int i = 0; i < 64; i++)
            o = fmaf(s_x[i * 128 + lane], s_w3[i], o);
        out[b * GSZ + lane] = fmaf(o, 500.0f, 1500.0f);
    }
}

// ----------------------------------------------------------------------------
extern "C" void kernel_launch(void* const* d_in, const int* in_sizes, int n_in,
                              void* d_out, int out_size)
{
    const float* z    = (const float*)d_in[0];
    const float* logP = (const float*)d_in[1];
    const float* hW0  = (const float*)d_in[2];
    const float* hb0  = (const float*)d_in[3];
    const float* hW1  = (const float*)d_in[4];
    const float* hb1  = (const float*)d_in[5];
    const float* hW2  = (const float*)d_in[6];
    const float* hb2  = (const float*)d_in[7];
    const float* hWo  = (const float*)d_in[8];
    const float* hbo  = (const float*)d_in[9];
    float* out = (float*)d_out;

    float *h0p, *h1p, *h2p, *wabp, *partp;
    cudaGetSymbolAddress((void**)&h0p, g_h0);
    cudaGetSymbolAddress((void**)&h1p, g_h1);
    cudaGetSymbolAddress((void**)&h2p, g_h2);
    cudaGetSymbolAddress((void**)&wabp, g_wab);
    cudaGetSymbolAddress((void**)&partp, g_part);

    // h0: 128x512x16, direct with bias+leaky
    gemm_k<32, 64, 16, 2, 4, 1, 1><<<dim3(HLDIM / 64, BSZ / 32, 1), 256>>>(
        z, hW0, hb0, h0p, BSZ, HLDIM, LDIM);

    // h1: 128x512x512, split-K x8
    gemm_k<64, 64, 16, 4, 4, 0, 8><<<dim3(HLDIM / 64, BSZ / 64, 8), 256>>>(
        h0p, hW1, hb1, partp, BSZ, HLDIM, HLDIM);
    reduce_bias<1, 8><<<(BSZ * HLDIM + 255) / 256, 256>>>(
        partp, hb1, h1p, BSZ, HLDIM);

    // h2
    gemm_k<64, 64, 16, 4, 4, 0, 8><<<dim3(HLDIM / 64, BSZ / 64, 8), 256>>>(
        h1p, hW2, hb2, partp, BSZ, HLDIM, HLDIM);
    reduce_bias<1, 8><<<(BSZ * HLDIM + 255) / 256, 256>>>(
        partp, hb2, h2p, BSZ, HLDIM);

    // wab: 128x8450x512, split-K x4, BM=128 tile
    gemm_k<128, 64, 16, 8, 4, 0, 4><<<dim3((OUTS + 63) / 64, 1, 4), 256>>>(
        h2p, hWo, hbo, partp, BSZ, OUTS, HLDIM);
    reduce_bias<0, 4><<<(BSZ * OUTS + 255) / 256, 256>>>(
        partp, hbo, wabp, BSZ, OUTS);

    // decoder
    const int smem_bytes = DEC_SMEM_FLOATS * (int)sizeof(float);
    cudaFuncSetAttribute(decoder_kernel,
                         cudaFuncAttributeMaxDynamicSharedMemorySize, smem_bytes);
    decoder_kernel<<<BSZ, DEC_NT, smem_bytes>>>(logP, wabp, out);
}